// round 12
// baseline (speedup 1.0000x reference)
#include <cuda_runtime.h>
#include <cstddef>

#define ALPHA_ 0.0001f
#define NN 16
#define TT 8
#define VV 256
#define FF 64
#define NVV (NN*VV*VV)
#define YS 68               // padded row stride: 272B, conflict-free patterns
#define NBLK 256

__device__ float g_sloss[NBLK];
__device__ float g_dloss[NN];
__device__ unsigned int g_counter = 0;

// grid (16 j-tiles, 16 n) = 256 blocks, 512 threads, 2 CTAs/SM (co-resident,
// desynchronized -> 8 warps/SMSP). Block owns 16 j-columns x all 256 i.
// Warp w: i-band (w>>1)*32, j-group (w&1)*8. Lane: li=lane&7, lj=lane>>3.
// Thread tile: 4 i (iband+li+8k) x 2 j (jg+4m+lj) -> 8 scalar accumulators.
// Max-trick: sum_f|yi-yj| = 2*sum_f max(yi,yj) - Ti - Tj (T = row sums).
extern "C" __global__ void __launch_bounds__(512, 2)
fused_kernel(const float* __restrict__ x, const float* __restrict__ a,
             float* __restrict__ out) {
    extern __shared__ float y[];            // [256][YS] y = xm*a (~68KB)
    __shared__ float red[512];
    __shared__ float Ts[VV];
    __shared__ float part[16][16];
    __shared__ float cs[16];
    __shared__ float sqw[16];
    __shared__ float wsum[16];

    const int tid  = threadIdx.x;
    const int lane = tid & 31;
    const int w    = tid >> 5;
    const int li   = lane & 7;
    const int lj   = lane >> 3;             // 0..3
    const int n    = blockIdx.y;
    const int jt   = blockIdx.x;            // 0..15
    const float* __restrict__ xm = x + (size_t)(n * TT + TT / 2) * (VV * FF);

    // Stage y = xm * a (tid&63 = fixed feature -> free per-f raw sums).
    const int   f  = tid & 63;
    const float af = __ldg(&a[f]);
    float Sx = 0.f, Sq = 0.f;
#pragma unroll
    for (int k = 0; k < 32; ++k) {
        int idx = tid + (k << 9);
        float v = xm[idx];
        y[(idx >> 6) * YS + f] = v * af;
        Sx += v;
        Sq = fmaf(v, v, Sq);
    }
    red[tid] = Sx;
#pragma unroll
    for (int o = 16; o; o >>= 1) Sq += __shfl_down_sync(~0u, Sq, o);
    if (lane == 0) sqw[w] = Sq;
    __syncthreads();

    // Row sums T_r (one-time).
    if (tid < VV) {
        const float4* p = reinterpret_cast<const float4*>(&y[tid * YS]);
        float s0 = 0.f, s1 = 0.f, s2 = 0.f, s3 = 0.f;
#pragma unroll
        for (int k = 0; k < 16; k += 4) {
            float4 v0 = p[k], v1 = p[k + 1], v2 = p[k + 2], v3 = p[k + 3];
            s0 += v0.x + v0.y + v0.z + v0.w;
            s1 += v1.x + v1.y + v1.z + v1.w;
            s2 += v2.x + v2.y + v2.z + v2.w;
            s3 += v3.x + v3.y + v3.z + v3.w;
        }
        Ts[tid] = (s0 + s1) + (s2 + s3);
    }

    // dloss_n = 2*(V*sum x^2 - sum_f (sum_i x)^2); valid because S's column
    // sums are exactly 1 (softmax axis) so sum(S@d2) == sum(d2).
    if (jt == 0 && w == 1) {
        float s1 = 0.f, s2 = 0.f;
#pragma unroll
        for (int r = 0; r < 8; ++r) {
            s1 += red[lane + (r << 6)];
            s2 += red[lane + 32 + (r << 6)];
        }
        float t  = s1 * s1 + s2 * s2;
        float sq = (lane < 16) ? sqw[lane] : 0.f;
#pragma unroll
        for (int o = 16; o; o >>= 1) {
            t  += __shfl_down_sync(~0u, t, o);
            sq += __shfl_down_sync(~0u, sq, o);
        }
        if (lane == 0) __stcg(&g_dloss[n], 2.f * ((float)VV * sq - t));
    }
    __syncthreads();

    const int iband = (w >> 1) * 32;
    const int jg    = (w & 1) * 8;
    const float* __restrict__ xib = y + (iband + li) * YS;            // +8k*YS
    const float* __restrict__ xjb = y + (jt * 16 + jg + lj) * YS;     // +4m*YS

    float acc[8];
#pragma unroll
    for (int p = 0; p < 8; ++p) acc[p] = 0.f;

#pragma unroll 4
    for (int h = 0; h < 16; ++h) {
        float4 xi[4], xj[2];
#pragma unroll
        for (int k = 0; k < 4; ++k)   // 8 li-distinct rows: conflict-free
            xi[k] = *reinterpret_cast<const float4*>(xib + k * 8 * YS + h * 4);
#pragma unroll
        for (int m = 0; m < 2; ++m)   // 4 lj-distinct rows: multicast groups
            xj[m] = *reinterpret_cast<const float4*>(xjb + m * 4 * YS + h * 4);
#pragma unroll
        for (int k = 0; k < 4; ++k)
#pragma unroll
            for (int m = 0; m < 2; ++m) {
                float s = acc[k * 2 + m];
                s += fmaxf(xi[k].x, xj[m].x);    // FMNMX (alu) + FADD (fma)
                s += fmaxf(xi[k].y, xj[m].y);
                s += fmaxf(xi[k].z, xj[m].z);
                s += fmaxf(xi[k].w, xj[m].w);
                acc[k * 2 + m] = s;
            }
    }

    // score = 2*acc - Ti - Tj (>= 0: relu is identity); exp + col partials.
    float Ti[4], Tj[2];
#pragma unroll
    for (int k = 0; k < 4; ++k) Ti[k] = Ts[iband + li + 8 * k];
#pragma unroll
    for (int m = 0; m < 2; ++m) Tj[m] = Ts[jt * 16 + jg + 4 * m + lj];

    float e[8];
    float cp[2] = {0.f, 0.f};
#pragma unroll
    for (int k = 0; k < 4; ++k)
#pragma unroll
        for (int m = 0; m < 2; ++m) {
            float v = __expf(2.f * acc[k * 2 + m] - Ti[k] - Tj[m]);
            e[k * 2 + m] = v;
            cp[m] += v;
        }
    // Reduce cp over li (8-lane groups share the same j-pair).
#pragma unroll
    for (int o = 4; o; o >>= 1) {
        cp[0] += __shfl_down_sync(~0u, cp[0], o);
        cp[1] += __shfl_down_sync(~0u, cp[1], o);
    }
    if (li == 0) {
        part[w][jg + lj]     = cp[0];
        part[w][jg + 4 + lj] = cp[1];
    }
    __syncthreads();
    if (tid < 16) {
        const int o = tid >> 3;              // column's j-group owner (w&1)
        float s = 0.f;
#pragma unroll
        for (int p = 0; p < 8; ++p) s += part[2 * p + o][tid];
        cs[tid] = 1.0f / s;
    }
    __syncthreads();

    float iv[2];
#pragma unroll
    for (int m = 0; m < 2; ++m) iv[m] = cs[jg + 4 * m + lj];

    // Normalize, write S, accumulate S^2.
    float sq2 = 0.f;
    float* ob = out + (size_t)n * (VV * VV) + jt * 16 + jg + lj;
#pragma unroll
    for (int k = 0; k < 4; ++k) {
        const size_t ro = (size_t)(iband + li + 8 * k) * VV;
#pragma unroll
        for (int m = 0; m < 2; ++m) {
            float Sv = e[k * 2 + m] * iv[m];
            ob[ro + 4 * m] = Sv;
            sq2 = fmaf(Sv, Sv, sq2);
        }
    }
#pragma unroll
    for (int o = 16; o; o >>= 1) sq2 += __shfl_down_sync(~0u, sq2, o);
    if (lane == 0) wsum[w] = sq2;
    __syncthreads();

    // Last-block finalize (graph-safe: counter reset each call).
    __shared__ unsigned int s_flag;
    const int bid = n * 16 + jt;
    if (tid == 0) {
        float t = 0.f;
#pragma unroll
        for (int k = 0; k < 16; ++k) t += wsum[k];
        __stcg(&g_sloss[bid], t);
        __threadfence();
        unsigned int c = atomicAdd(&g_counter, 1u);
        s_flag = (c == NBLK - 1) ? 1u : 0u;
    }
    __syncthreads();
    if (s_flag && w == 0) {
        __threadfence();
        float s = 0.f;
#pragma unroll
        for (int k = 0; k < 8; ++k) s += __ldcg(&g_sloss[lane + (k << 5)]);
        float dl = (lane < NN) ? __ldcg(&g_dloss[lane]) : 0.f;
#pragma unroll
        for (int o = 16; o; o >>= 1) {
            s  += __shfl_down_sync(~0u, s, o);
            dl += __shfl_down_sync(~0u, dl, o);
        }
        if (lane == 0) {
            out[NVV]     = s * (ALPHA_ / (float)NN);
            out[NVV + 1] = dl * ALPHA_;
            g_counter = 0;
        }
    }
}

extern "C" void kernel_launch(void* const* d_in, const int* in_sizes, int n_in,
                              void* d_out, int out_size) {
    const float* x = (const float*)d_in[0];
    const float* a = (const float*)d_in[1];
    if (n_in >= 2 && in_sizes[0] == FF) {      // defensive input-order check
        const float* t = x; x = a; a = t;
    }
    float* out = (float*)d_out;

    const int smem = VV * YS * (int)sizeof(float);
    cudaFuncSetAttribute(fused_kernel,
                         cudaFuncAttributeMaxDynamicSharedMemorySize, smem);
    fused_kernel<<<dim3(16, NN), 512, smem>>>(x, a, out);
}

// round 13
// speedup vs baseline: 1.0428x; 1.0428x over previous
#include <cuda_runtime.h>
#include <cstddef>

#define ALPHA_ 0.0001f
#define NN 16
#define TT 8
#define VV 256
#define FF 64
#define NVV (NN*VV*VV)
#define YS 68               // padded row stride: conflict-free column reads
#define NBLK 144            // 9 tile-groups x 16 n; <=148 SMs -> co-resident

__device__ float g_sloss[NBLK];
__device__ float g_dloss[NN];
__device__ float g_colsum[NN * VV];
__device__ unsigned int g_c1 = 0, g_counter = 0;
__device__ volatile unsigned int g_r1 = 0;

// grid (9, 16), 512 threads, 1 CTA/SM, all 144 blocks co-resident.
// The 256x256 exp(score) matrix is SYMMETRIC: only the 36 upper tiles
// (32x32) are computed (0.56x pairs). Warp w owns tile t=b*4+(w>>2) and an
// 8-column strip (w&3); thread tile 4i x 2j. e stays IN REGISTERS across a
// single grid barrier; phase C normalizes and writes S to (i,j) AND (j,i).
extern "C" __global__ void __launch_bounds__(512, 1)
fused_kernel(const float* __restrict__ x, const float* __restrict__ a,
             float* __restrict__ out) {
    extern __shared__ float y[];            // [256][YS] y = xm*a (~68KB)
    __shared__ float red[512];
    __shared__ float Ts[VV];                // row sums of y (max-trick)
    __shared__ float colpart[VV];           // block-local colsum partials
    __shared__ float invs[VV];
    __shared__ float sqw[16];
    __shared__ float wsum[16];
    __shared__ unsigned int s_flag;

    const int tid  = threadIdx.x;
    const int lane = tid & 31;
    const int w    = tid >> 5;
    const int li   = lane & 7;
    const int g4   = lane >> 3;             // 0..3
    const int b    = blockIdx.x;            // 0..8
    const int n    = blockIdx.y;
    const float* __restrict__ xm = x + (size_t)(n * TT + TT / 2) * (VV * FF);
    float* __restrict__ on = out + (size_t)n * (VV * VV);

    // Stage y = xm * a (tid&63 = fixed feature -> free per-f raw sums).
    const int   f  = tid & 63;
    const float af = __ldg(&a[f]);
    float Sx = 0.f, Sq = 0.f;
#pragma unroll
    for (int k = 0; k < 32; ++k) {
        int idx = tid + (k << 9);
        float v = xm[idx];
        y[(idx >> 6) * YS + f] = v * af;
        Sx += v;
        Sq = fmaf(v, v, Sq);
    }
    red[tid] = Sx;
#pragma unroll
    for (int o = 16; o; o >>= 1) Sq += __shfl_down_sync(~0u, Sq, o);
    if (lane == 0) sqw[w] = Sq;
    if (tid < VV) colpart[tid] = 0.f;
    __syncthreads();

    // Row sums T_r (one-time, warps 0-7).
    if (tid < VV) {
        const float4* p = reinterpret_cast<const float4*>(&y[tid * YS]);
        float s0 = 0.f, s1 = 0.f, s2 = 0.f, s3 = 0.f;
#pragma unroll
        for (int k = 0; k < 16; k += 4) {
            float4 v0 = p[k], v1 = p[k + 1], v2 = p[k + 2], v3 = p[k + 3];
            s0 += v0.x + v0.y + v0.z + v0.w;
            s1 += v1.x + v1.y + v1.z + v1.w;
            s2 += v2.x + v2.y + v2.z + v2.w;
            s3 += v3.x + v3.y + v3.z + v3.w;
        }
        Ts[tid] = (s0 + s1) + (s2 + s3);
    }

    // dloss_n = 2*(V*sum x^2 - sum_f (sum_i x)^2); valid since S's column
    // sums are exactly 1 (softmax axis) -> sum(S@d2) == sum(d2). Warp 8.
    if (b == 0 && w == 8) {
        float s1 = 0.f, s2 = 0.f;
#pragma unroll
        for (int r = 0; r < 8; ++r) {
            s1 += red[lane + (r << 6)];
            s2 += red[lane + 32 + (r << 6)];
        }
        float t  = s1 * s1 + s2 * s2;
        float sq = (lane < 16) ? sqw[lane] : 0.f;
#pragma unroll
        for (int o = 16; o; o >>= 1) {
            t  += __shfl_down_sync(~0u, t, o);
            sq += __shfl_down_sync(~0u, sq, o);
        }
        if (lane == 0) __stcg(&g_dloss[n], 2.f * ((float)VV * sq - t));
    }
    __syncthreads();

    // ---- Phase A: warp's tile (r, c), r <= c, from triangle unrank.
    int t = b * 4 + (w >> 2);
    int r = 0;
    while (t >= 8 - r) { t -= 8 - r; ++r; }
    const int c  = r + t;
    const int c0 = ((w & 3) << 3) + (g4 << 1);  // col offset in tile (+0,+1)

    const float* __restrict__ xib = y + (r * 32 + li) * YS;   // +8k*YS
    const float* __restrict__ xjb = y + (c * 32 + c0) * YS;   // +m*YS

    float acc[8];
#pragma unroll
    for (int p = 0; p < 8; ++p) acc[p] = 0.f;

#pragma unroll 4
    for (int h = 0; h < 16; ++h) {
        float4 xi[4], xj[2];
#pragma unroll
        for (int k = 0; k < 4; ++k)
            xi[k] = *reinterpret_cast<const float4*>(xib + k * 8 * YS + h * 4);
#pragma unroll
        for (int m = 0; m < 2; ++m)
            xj[m] = *reinterpret_cast<const float4*>(xjb + m * YS + h * 4);
#pragma unroll
        for (int k = 0; k < 4; ++k)
#pragma unroll
            for (int m = 0; m < 2; ++m) {
                float s = acc[k * 2 + m];
                s += fmaxf(xi[k].x, xj[m].x);    // FMNMX (alu) + FADD (fma)
                s += fmaxf(xi[k].y, xj[m].y);
                s += fmaxf(xi[k].z, xj[m].z);
                s += fmaxf(xi[k].w, xj[m].w);
                acc[k * 2 + m] = s;
            }
    }

    // score = 2*acc - Ti - Tj (>= 0: relu identity); exp.
    float Ti[4], Tj[2];
#pragma unroll
    for (int k = 0; k < 4; ++k) Ti[k] = Ts[r * 32 + li + 8 * k];
#pragma unroll
    for (int m = 0; m < 2; ++m) Tj[m] = Ts[c * 32 + c0 + m];

    float e[8];
    float cp0 = 0.f, cp1 = 0.f;
#pragma unroll
    for (int k = 0; k < 4; ++k) {
        float v0 = __expf(2.f * acc[k * 2]     - Ti[k] - Tj[0]);
        float v1 = __expf(2.f * acc[k * 2 + 1] - Ti[k] - Tj[1]);
        e[k * 2] = v0; e[k * 2 + 1] = v1;
        cp0 += v0; cp1 += v1;
    }
    // Column partials: reduce over li (xor 1,2,4 stays in 8-lane group).
#pragma unroll
    for (int o = 1; o < 8; o <<= 1) {
        cp0 += __shfl_xor_sync(~0u, cp0, o);
        cp1 += __shfl_xor_sync(~0u, cp1, o);
    }
    if (li == 0) {
        atomicAdd(&colpart[c * 32 + c0],     cp0);
        atomicAdd(&colpart[c * 32 + c0 + 1], cp1);
    }
    // Row sums double as colsums of the mirrored tile (off-diag only).
    if (r != c) {
        float rp[4];
#pragma unroll
        for (int k = 0; k < 4; ++k) rp[k] = e[k * 2] + e[k * 2 + 1];
#pragma unroll
        for (int o = 8; o < 32; o <<= 1)
#pragma unroll
            for (int k = 0; k < 4; ++k)
                rp[k] += __shfl_xor_sync(~0u, rp[k], o);
        if (lane < 8)
#pragma unroll
            for (int k = 0; k < 4; ++k)
                atomicAdd(&colpart[r * 32 + li + 8 * k], rp[k]);
    }
    __syncthreads();
    if (tid < VV) {
        atomicAdd(&g_colsum[n * VV + tid], colpart[tid]);
        __threadfence();                     // publish before barrier
    }

    // ---- Single grid barrier (all blocks co-resident).
    __syncthreads();
    if (tid == 0) {
        __threadfence();
        if (atomicAdd(&g_c1, 1u) == NBLK - 1) g_r1 = 1u;
        else while (g_r1 == 0u) __nanosleep(64);
        __threadfence();
    }
    __syncthreads();

    if (tid < VV) invs[tid] = 1.0f / __ldcg(&g_colsum[n * VV + tid]);
    __syncthreads();

    // ---- Phase C: normalize FROM REGISTERS; write direct + mirror.
    float ivc0 = invs[c * 32 + c0], ivc1 = invs[c * 32 + c0 + 1];
    float ivr[4];
#pragma unroll
    for (int k = 0; k < 4; ++k) ivr[k] = invs[r * 32 + li + 8 * k];

    float sq2 = 0.f;
#pragma unroll
    for (int k = 0; k < 4; ++k) {
        const int gi = r * 32 + li + 8 * k;
        float S0 = e[k * 2] * ivc0, S1 = e[k * 2 + 1] * ivc1;
        *reinterpret_cast<float2*>(on + (size_t)gi * VV + c * 32 + c0) =
            make_float2(S0, S1);
        sq2 = fmaf(S0, S0, fmaf(S1, S1, sq2));
        if (r != c) {
            float M0 = e[k * 2] * ivr[k], M1 = e[k * 2 + 1] * ivr[k];
            on[(size_t)(c * 32 + c0)     * VV + gi] = M0;
            on[(size_t)(c * 32 + c0 + 1) * VV + gi] = M1;
            sq2 = fmaf(M0, M0, fmaf(M1, M1, sq2));
        }
    }
#pragma unroll
    for (int o = 16; o; o >>= 1) sq2 += __shfl_down_sync(~0u, sq2, o);
    if (lane == 0) wsum[w] = sq2;
    __syncthreads();

    // ---- Last-block finalize (graph-safe: ALL state reset each call).
    const int bid = n * 9 + b;
    if (tid == 0) {
        float tt = 0.f;
#pragma unroll
        for (int k = 0; k < 16; ++k) tt += wsum[k];
        __stcg(&g_sloss[bid], tt);
        __threadfence();
        unsigned int cdone = atomicAdd(&g_counter, 1u);
        s_flag = (cdone == NBLK - 1) ? 1u : 0u;
    }
    __syncthreads();
    if (s_flag) {
        for (int idx = tid; idx < NN * VV; idx += 512)
            __stcg(&g_colsum[idx], 0.f);     // reset for next replay
        if (w == 0) {
            __threadfence();
            float s = 0.f;
#pragma unroll
            for (int k = 0; k < 5; ++k) {
                int idx = lane + (k << 5);
                if (idx < NBLK) s += __ldcg(&g_sloss[idx]);
            }
            float dl = (lane < NN) ? __ldcg(&g_dloss[lane]) : 0.f;
#pragma unroll
            for (int o = 16; o; o >>= 1) {
                s  += __shfl_down_sync(~0u, s, o);
                dl += __shfl_down_sync(~0u, dl, o);
            }
            if (lane == 0) {
                out[NVV]     = s * (ALPHA_ / (float)NN);
                out[NVV + 1] = dl * ALPHA_;
                g_c1 = 0; g_r1 = 0; g_counter = 0;   // reset barrier state
            }
        }
    }
}

extern "C" void kernel_launch(void* const* d_in, const int* in_sizes, int n_in,
                              void* d_out, int out_size) {
    const float* x = (const float*)d_in[0];
    const float* a = (const float*)d_in[1];
    if (n_in >= 2 && in_sizes[0] == FF) {      // defensive input-order check
        const float* t = x; x = a; a = t;
    }
    float* out = (float*)d_out;

    const int smem = VV * YS * (int)sizeof(float);
    cudaFuncSetAttribute(fused_kernel,
                         cudaFuncAttributeMaxDynamicSharedMemorySize, smem);
    fused_kernel<<<dim3(9, NN), 512, smem>>>(x, a, out);
}